// round 13
// baseline (speedup 1.0000x reference)
#include <cuda_runtime.h>
#include <cuda.h>
#include <cuda_bf16.h>
#include <math.h>

#define N_NODES 19
#define N_T     4096
#define LATENT  512
#define HID     2048
#define N_EDGES 342

// ---------------- scratch (__device__ globals; no allocs allowed) -----------
__device__ __align__(16) float g_accA[N_NODES * N_T];
__device__ __align__(16) float g_accB[N_NODES * N_T];
__device__ __align__(16) float g_accC[N_NODES * N_T];
__device__ __align__(16) float g_v[LATENT];
__device__ float g_adjf[N_NODES * N_NODES]; // dense edge-count matrix [dst][src]

// ---------------- K0: adjacency + zero all accumulators ---------------------
__global__ void init_kernel(const void* __restrict__ eidx,
                            float* __restrict__ accA,
                            float* __restrict__ accB,
                            float* __restrict__ accC,
                            float* __restrict__ v) {
    int t = threadIdx.x;
    if (blockIdx.x == 0) {
        __shared__ int cnt[N_NODES * N_NODES];
        __shared__ int s_i64;
        for (int i = t; i < N_NODES * N_NODES; i += blockDim.x) cnt[i] = 0;
        if (t == 0) {
            const long long* e64 = (const long long*)eidx;
            int ok = 1;
            for (int i = 0; i < N_EDGES; ++i) {
                long long x = e64[i];
                if (x < 0 || x >= N_NODES) { ok = 0; break; }
            }
            s_i64 = ok;
        }
        __syncthreads();
        const long long* e64 = (const long long*)eidx;
        const int*       e32 = (const int*)eidx;
        for (int e = t; e < N_EDGES; e += blockDim.x) {
            int src, dst;
            if (s_i64) { src = (int)e64[e]; dst = (int)e64[N_EDGES + e]; }
            else       { src = e32[e];      dst = e32[N_EDGES + e]; }
            atomicAdd(&cnt[dst * N_NODES + src], 1);
        }
        __syncthreads();
        for (int i = t; i < N_NODES * N_NODES; i += blockDim.x)
            g_adjf[i] = (float)cnt[i];
        for (int i = t; i < LATENT; i += blockDim.x) v[i] = 0.0f;
    }
    const int n4 = (N_NODES * N_T) >> 2;
    float4 zz = make_float4(0.f, 0.f, 0.f, 0.f);
    for (int q = blockIdx.x * blockDim.x + t; q < n4;
         q += gridDim.x * blockDim.x) {
        reinterpret_cast<float4*>(accA)[q] = zz;
        reinterpret_cast<float4*>(accB)[q] = zz;
        reinterpret_cast<float4*>(accC)[q] = zz;
    }
}

// ---------------- TMA-fed split-K GEMM --------------------------------------
// Cacc += stage(Ain)[19, K] @ W[K, N].  128 threads x 2 cols = 256-col tile.
// NEW (R13): W is fetched by the TMA engine (cp.async.bulk.tensor.2d) into a
// 3-stage smem ring against mbarriers -- warp issue slots / scoreboards /
// L1tex queue are entirely out of the fetch path (the limiter every warp-
// issued-load variant hit). Stage = 16 k-rows x 256 cols = 16 KB.
// A staged once as duplicated {a,a} pairs; epilogue: red.global.add.v2.f32.
// MODE 0: stage = agg(Ain); 1: relu(Ain+bias); 2: agg(relu(Ain+bias)).
#define RING_S 3
#define STG_K  16
#define STG_BYTES (STG_K * 256 * 4)   // 16384

template<int KC, int MODE>
__global__ __launch_bounds__(128) void gemm_tma(
        const __grid_constant__ CUtensorMap tmap,
        const float* __restrict__ Ain, const float* __restrict__ bias,
        float* __restrict__ Cacc,
        float* __restrict__ zbuf, int zn, int K, int N) {
    extern __shared__ __align__(128) char dsm[];
    float* buf = (float*)dsm;                                   // 3 x 16KB ring
    unsigned long long* mbar =
        (unsigned long long*)(dsm + RING_S * STG_BYTES);        // 3 mbarriers
    unsigned long long* sA =
        (unsigned long long*)(dsm + RING_S * STG_BYTES + 64);   // [19][KC] pairs
    float* sRaw = (float*)(sA + N_NODES * KC);                  // [19][KC]
    __shared__ float s_adj[N_NODES * N_NODES];

    const int tid = threadIdx.x;
    const int colbase = blockIdx.x * 256;
    const int kbeg = blockIdx.y * KC;
    constexpr int NST = KC / STG_K;

    const unsigned buf_u32  = (unsigned)__cvta_generic_to_shared(buf);
    const unsigned mbar_u32 = (unsigned)__cvta_generic_to_shared(mbar);

    // init mbarriers (tid 0, also the sole TMA issuer -> no extra fence needed)
    if (tid == 0) {
#pragma unroll
        for (int s = 0; s < RING_S; ++s)
            asm volatile("mbarrier.init.shared.b64 [%0], 1;"
                         :: "r"(mbar_u32 + s * 8) : "memory");
    }
    __syncthreads();

    // kick off the ring: stages 0..S-1
    if (tid == 0) {
#pragma unroll
        for (int s = 0; s < RING_S && s < NST; ++s) {
            unsigned mb = mbar_u32 + s * 8;
            asm volatile("mbarrier.arrive.expect_tx.shared.b64 _, [%0], %1;"
                         :: "r"(mb), "r"((unsigned)STG_BYTES) : "memory");
            asm volatile(
                "cp.async.bulk.tensor.2d.shared::cta.global.tile"
                ".mbarrier::complete_tx::bytes [%0], [%1, {%2, %3}], [%4];"
                :: "r"(buf_u32 + s * STG_BYTES), "l"(&tmap),
                   "r"(colbase), "r"(kbeg + s * STG_K), "r"(mb)
                : "memory");
        }
    }

    // lazy zeroing for a future accumulator (overlaps TMA latency)
    if (zbuf) {
        int n4 = zn >> 2;
        float4 zz = make_float4(0.f, 0.f, 0.f, 0.f);
        for (int q = (blockIdx.y * gridDim.x + blockIdx.x) * 128 + tid;
             q < n4; q += gridDim.x * gridDim.y * 128)
            reinterpret_cast<float4*>(zbuf)[q] = zz;
    }
    if (MODE != 1) {
        for (int i = tid; i < N_NODES * N_NODES; i += 128)
            s_adj[i] = g_adjf[i];
    }

    // ---- stage A slab once (fused epilogue/agg), duplicated pairs ----
    for (int i = tid; i < N_NODES * KC; i += 128) {
        int r = i / KC, k = i - r * KC;
        float a = Ain[r * K + kbeg + k];
        if (MODE >= 1) a = fmaxf(a + bias[kbeg + k], 0.0f);
        if (MODE == 1) {
            unsigned long long p;
            asm("mov.b64 %0, {%1, %1};" : "=l"(p) : "f"(a));
            sA[i] = p;
        } else {
            sRaw[i] = a;
        }
    }
    __syncthreads();
    if (MODE != 1) {
        for (int i = tid; i < N_NODES * KC; i += 128) {
            int r = i / KC, k = i - r * KC;
            float a = sRaw[r * KC + k];
#pragma unroll
            for (int s = 0; s < N_NODES; ++s)
                a += s_adj[r * N_NODES + s] * sRaw[s * KC + k];
            unsigned long long p;
            asm("mov.b64 %0, {%1, %1};" : "=l"(p) : "f"(a));
            sA[i] = p;
        }
        __syncthreads();
    }

    unsigned long long acc[N_NODES];
#pragma unroll
    for (int r = 0; r < N_NODES; ++r) acc[r] = 0ull;

#pragma unroll 1
    for (int st = 0; st < NST; ++st) {
        const int b = st % RING_S;
        const unsigned mb = mbar_u32 + b * 8;
        const unsigned ph = (unsigned)((st / RING_S) & 1);
        // wait for stage st's 16KB to land
        asm volatile(
            "{\n\t.reg .pred p;\n"
            "WAIT_%=:\n\t"
            "mbarrier.try_wait.parity.shared.b64 p, [%0], %1;\n\t"
            "@!p bra WAIT_%=;\n\t}"
            :: "r"(mb), "r"(ph) : "memory");

        const float* wb = buf + b * (STG_K * 256);
#pragma unroll
        for (int kk = 0; kk < STG_K; kk += 2) {
            unsigned long long w0 = *reinterpret_cast<const unsigned long long*>(
                                        wb + kk * 256 + 2 * tid);
            unsigned long long w1 = *reinterpret_cast<const unsigned long long*>(
                                        wb + (kk + 1) * 256 + 2 * tid);
            const unsigned long long* ab = sA + st * STG_K + kk;
#pragma unroll
            for (int r = 0; r < N_NODES; ++r) {
                ulonglong2 ap = *reinterpret_cast<const ulonglong2*>(ab + r * KC);
                asm("fma.rn.f32x2 %0, %1, %2, %0;"
                    : "+l"(acc[r]) : "l"(ap.x), "l"(w0));
                asm("fma.rn.f32x2 %0, %1, %2, %0;"
                    : "+l"(acc[r]) : "l"(ap.y), "l"(w1));
            }
        }
        __syncthreads();   // everyone done reading buffer b
        if (tid == 0 && st + RING_S < NST) {
            asm volatile("mbarrier.arrive.expect_tx.shared.b64 _, [%0], %1;"
                         :: "r"(mb), "r"((unsigned)STG_BYTES) : "memory");
            asm volatile(
                "cp.async.bulk.tensor.2d.shared::cta.global.tile"
                ".mbarrier::complete_tx::bytes [%0], [%1, {%2, %3}], [%4];"
                :: "r"(buf_u32 + b * STG_BYTES), "l"(&tmap),
                   "r"(colbase), "r"(kbeg + (st + RING_S) * STG_K), "r"(mb)
                : "memory");
        }
    }

    // ---- epilogue: one 64-bit reduction per row ----
    const int col = colbase + tid * 2;
#pragma unroll
    for (int r = 0; r < N_NODES; ++r) {
        float2 p = *reinterpret_cast<float2*>(&acc[r]);
        asm volatile("red.global.add.v2.f32 [%0], {%1, %2};"
                     :: "l"(Cacc + r * N + col), "f"(p.x), "f"(p.y)
                     : "memory");
    }
}

// ---------------- FC1 fused: flat = acc + b2b (also written to out1);
//                  v[512] += flat @ Wc1 --------------------------------------
__global__ __launch_bounds__(128) void fc1_kernel(
        const float* __restrict__ acc, const float* __restrict__ b2b,
        const float* __restrict__ Wc1, float* __restrict__ v,
        float* __restrict__ out1, int rows_per) {
    const int ROWS = N_NODES * N_T;
    int t = threadIdx.x;                       // cols 4t..4t+3
    int r0 = blockIdx.x * rows_per;
    int r1 = min(r0 + rows_per, ROWS);
    float4 s = make_float4(0.f, 0.f, 0.f, 0.f);
    int i = r0;
    for (; i + 8 <= r1; i += 8) {
        float f[8];
        float4 w[8];
#pragma unroll
        for (int u = 0; u < 8; ++u) {
            f[u] = acc[i + u] + b2b[(i + u) & (N_T - 1)];
            w[u] = *reinterpret_cast<const float4*>(
                       &Wc1[(size_t)(i + u) * LATENT + 4 * t]);
        }
#pragma unroll
        for (int u = 0; u < 8; ++u) {
            if (t == ((i + u) & 127)) out1[i + u] = f[u];
            s.x += f[u] * w[u].x; s.y += f[u] * w[u].y;
            s.z += f[u] * w[u].z; s.w += f[u] * w[u].w;
        }
    }
    for (; i < r1; ++i) {
        float f = acc[i] + b2b[i & (N_T - 1)];
        if (t == (i & 127)) out1[i] = f;
        float4 w = *reinterpret_cast<const float4*>(
                       &Wc1[(size_t)i * LATENT + 4 * t]);
        s.x += f * w.x; s.y += f * w.y; s.z += f * w.z; s.w += f * w.w;
    }
    asm volatile("red.global.add.v4.f32 [%0], {%1, %2, %3, %4};"
                 :: "l"(v + 4 * t), "f"(s.x), "f"(s.y), "f"(s.z), "f"(s.w)
                 : "memory");
}

// ---------------- FC2 + sigmoid ---------------------------------------------
__global__ void fc2_kernel(const float* __restrict__ v,
                           const float* __restrict__ bc1,
                           const float* __restrict__ Wc2,
                           const float* __restrict__ bc2,
                           float* __restrict__ out) {
    __shared__ float red[LATENT];
    int j = threadIdx.x;
    red[j] = (v[j] + bc1[j]) * Wc2[j];
    __syncthreads();
    for (int s = LATENT / 2; s > 0; s >>= 1) {
        if (j < s) red[j] += red[j + s];
        __syncthreads();
    }
    if (j == 0) out[0] = 1.0f / (1.0f + expf(-(red[0] + bc2[0])));
}

// ---------------- host helpers ----------------------------------------------
typedef CUresult (*EncodeFn)(
    CUtensorMap*, CUtensorMapDataType, cuuint32_t, void*,
    const cuuint64_t*, const cuuint64_t*, const cuuint32_t*, const cuuint32_t*,
    CUtensorMapInterleave, CUtensorMapSwizzle, CUtensorMapL2promotion,
    CUtensorMapFloatOOBfill);

static EncodeFn get_encode_fn() {
    static EncodeFn fn = nullptr;
    if (!fn) {
        cudaDriverEntryPointQueryResult qres;
        void* p = nullptr;
        cudaGetDriverEntryPoint("cuTensorMapEncodeTiled", &p,
                                cudaEnableDefault, &qres);
        fn = (EncodeFn)p;
    }
    return fn;
}

static void make_wmap(CUtensorMap* map, const float* W, int K, int N) {
    cuuint64_t dims[2]    = {(cuuint64_t)N, (cuuint64_t)K};
    cuuint64_t strides[1] = {(cuuint64_t)N * 4};
    cuuint32_t box[2]     = {256, STG_K};
    cuuint32_t estr[2]    = {1, 1};
    get_encode_fn()(map, CU_TENSOR_MAP_DATA_TYPE_FLOAT32, 2, (void*)W,
                    dims, strides, box, estr,
                    CU_TENSOR_MAP_INTERLEAVE_NONE, CU_TENSOR_MAP_SWIZZLE_NONE,
                    CU_TENSOR_MAP_L2_PROMOTION_L2_128B,
                    CU_TENSOR_MAP_FLOAT_OOB_FILL_NONE);
}

static inline int tma_smem(int kc) {
    return RING_S * STG_BYTES + 64 + kc * N_NODES * 8 + kc * N_NODES * 4;
}

// ---------------- launch ----------------------------------------------------
extern "C" void kernel_launch(void* const* d_in, const int* in_sizes, int n_in,
                              void* d_out, int out_size) {
    const float* z    = (const float*)d_in[0];
    const void*  eidx = d_in[1];
    const float* W1a  = (const float*)d_in[2];
    const float* b1a  = (const float*)d_in[3];
    const float* W1b  = (const float*)d_in[4];
    const float* b1b  = (const float*)d_in[5];
    const float* W2a  = (const float*)d_in[6];
    const float* b2a  = (const float*)d_in[7];
    const float* W2b  = (const float*)d_in[8];
    const float* b2b  = (const float*)d_in[9];
    const float* Wc1  = (const float*)d_in[10];
    const float* bc1  = (const float*)d_in[11];
    const float* Wc2  = (const float*)d_in[12];
    const float* bc2  = (const float*)d_in[13];
    float* out = (float*)d_out;

    float *accA, *accB, *accC, *v;
    cudaGetSymbolAddress((void**)&accA, g_accA);
    cudaGetSymbolAddress((void**)&accB, g_accB);
    cudaGetSymbolAddress((void**)&accC, g_accC);
    cudaGetSymbolAddress((void**)&v,    g_v);

    const int nNT = N_NODES * N_T;   // 77824

    static int attr_done = 0;
    if (!attr_done) {
        cudaFuncSetAttribute(gemm_tma<32, 0>,
            cudaFuncAttributeMaxDynamicSharedMemorySize, tma_smem(32));
        cudaFuncSetAttribute(gemm_tma<32, 1>,
            cudaFuncAttributeMaxDynamicSharedMemorySize, tma_smem(32));
        cudaFuncSetAttribute(gemm_tma<64, 2>,
            cudaFuncAttributeMaxDynamicSharedMemorySize, tma_smem(64));
        cudaFuncSetAttribute(gemm_tma<64, 1>,
            cudaFuncAttributeMaxDynamicSharedMemorySize, tma_smem(64));
        attr_done = 1;
    }

    // tensormaps (host-side; captured into graph as kernel params)
    CUtensorMap m1a, m1b, m2a, m2b;
    make_wmap(&m1a, W1a, LATENT, HID);
    make_wmap(&m1b, W1b, HID, HID);
    make_wmap(&m2a, W2a, HID, N_T);
    make_wmap(&m2b, W2b, N_T, N_T);

    // K0: adjacency + zero accA/accB/accC/v
    init_kernel<<<148, 256>>>(eidx, accA, accB, accC, v);

    // g1a: accA = agg(z) @ W1a          [19,512]x[512,2048]   128 blocks
    gemm_tma<32, 0><<<dim3(HID / 256, LATENT / 32), 128, tma_smem(32)>>>(
        m1a, z, nullptr, accA, nullptr, 0, LATENT, HID);

    // g1b: accB = relu(accA+b1a) @ W1b  [19,2048]x[2048,2048] 512 blocks
    gemm_tma<32, 1><<<dim3(HID / 256, HID / 32), 128, tma_smem(32)>>>(
        m1b, accA, b1a, accB, nullptr, 0, HID, HID);

    // g2a: accC = agg(relu(accB+b1b)) @ W2a  [19,2048]x[2048,4096] 512 blocks
    //      (also lazily zeroes accA for g2b)
    gemm_tma<64, 2><<<dim3(N_T / 256, HID / 64), 128, tma_smem(64)>>>(
        m2a, accB, b1b, accC, accA, nNT, HID, N_T);

    // g2b: accA = relu(accC+b2a) @ W2b  [19,4096]x[4096,4096] 1024 blocks
    gemm_tma<64, 1><<<dim3(N_T / 256, N_T / 64), 128, tma_smem(64)>>>(
        m2b, accC, b2a, accA, nullptr, 0, N_T, N_T);

    // classifier: epilogue (+b2b, write out[1:]) fused into FC1
    fc1_kernel<<<1184, 128>>>(accA, b2b, Wc1, v, out + 1, 66);
    fc2_kernel<<<1, 512>>>(v, bc1, Wc2, bc2, out);
}